// round 4
// baseline (speedup 1.0000x reference)
#include <cuda_runtime.h>

// SpectrogramAugmentation: B=64, C=2, F=128, T=2048, fp32. HBM-bound at the
// traffic floor (~293 MB) and near the mixed-stream HBM rate ceiling.
// R4: persistent grid-stride over rows — 2368 resident blocks each walk ~7 rows,
// so independent LDG.256s from consecutive rows pipeline within a thread and
// the ~14 launch waves collapse into one.
// Traffic-minimal branches per row:
//   - non-apply batch: out = spec                (no noise read)
//   - apply + freq-masked row: out = 0.01*noise  (no spec read)
//   - apply + kept row: out = (timekeep? spec:0) + 0.01*noise

#define SA_B 64
#define SA_C 2
#define SA_F 128
#define SA_T 2048
#define SA_ROWS (SA_B * SA_C * SA_F)
#define SA_FREQ_PARAM 20.0f
#define SA_TIME_PARAM 40.0f
#define SA_NOISE_STD 0.01f
#define SA_P_APPLY 0.5f

#define SA_GRID 2368   // 148 SMs * 16

struct f8 { float v[8]; };

__device__ __forceinline__ f8 ldg256cs(const float* p) {
    f8 r;
    asm volatile("ld.global.cs.v8.f32 {%0,%1,%2,%3,%4,%5,%6,%7}, [%8];"
                 : "=f"(r.v[0]), "=f"(r.v[1]), "=f"(r.v[2]), "=f"(r.v[3]),
                   "=f"(r.v[4]), "=f"(r.v[5]), "=f"(r.v[6]), "=f"(r.v[7])
                 : "l"(p));
    return r;
}

__device__ __forceinline__ void stg256cs(float* p, const f8& r) {
    asm volatile("st.global.cs.v8.f32 [%0], {%1,%2,%3,%4,%5,%6,%7,%8};"
                 :: "l"(p),
                    "f"(r.v[0]), "f"(r.v[1]), "f"(r.v[2]), "f"(r.v[3]),
                    "f"(r.v[4]), "f"(r.v[5]), "f"(r.v[6]), "f"(r.v[7])
                 : "memory");
}

__global__ __launch_bounds__(256)
void specaug_kernel(const float* __restrict__ spec,
                    const float* __restrict__ apply_u,
                    const float* __restrict__ f_width_u,
                    const float* __restrict__ f_start_u,
                    const float* __restrict__ t_width_u,
                    const float* __restrict__ t_start_u,
                    const float* __restrict__ noise,
                    float* __restrict__ out) {
    const int t0 = threadIdx.x * 8;             // this thread's 8 time samples

    for (int row = blockIdx.x; row < SA_ROWS; row += SA_GRID) {
        const int f = row & (SA_F - 1);
        const int b = row >> 8;                 // row / (C*F) = row / 256
        const long long base = (long long)row * SA_T + t0;

        const float* sp = spec + base;
        float*       op = out  + base;

        const bool apply = (__ldg(&apply_u[b]) <= SA_P_APPLY);
        if (!apply) {
            // exact passthrough: no noise read
            stg256cs(op, ldg256cs(sp));
            continue;
        }

        const float* np = noise + base;

        // --- frequency mask for this f (2 masks, no clamp_min_one) ---
        bool fhit = false;
        #pragma unroll
        for (int k = 0; k < 2; k++) {
            const int   w   = (int)floorf(__ldg(&f_width_u[b * 2 + k]) * SA_FREQ_PARAM);
            const float rng = (float)(SA_F - w);
            const int   s0  = (int)floorf(__ldg(&f_start_u[b * 2 + k]) * rng);
            fhit = fhit || (f >= s0 && f < s0 + w);
        }

        if (fhit) {
            // whole row frequency-masked: out = 0.01*noise, no spec read
            const f8 n = ldg256cs(np);
            f8 o;
            #pragma unroll
            for (int j = 0; j < 8; j++) o.v[j] = n.v[j] * SA_NOISE_STD;
            stg256cs(op, o);
            continue;
        }

        // --- time masks (2 masks, clamp_min_one on range) ---
        int ts0[2], te[2];
        #pragma unroll
        for (int k = 0; k < 2; k++) {
            const int w = (int)floorf(__ldg(&t_width_u[b * 2 + k]) * SA_TIME_PARAM);
            float rng = (float)(SA_T - w);
            if (rng < 1.0f) rng = 1.0f;
            const int s0 = (int)floorf(__ldg(&t_start_u[b * 2 + k]) * rng);
            ts0[k] = s0;
            te[k]  = s0 + w;
        }

        const f8 s = ldg256cs(sp);
        const f8 n = ldg256cs(np);
        f8 o;
        #pragma unroll
        for (int j = 0; j < 8; j++) {
            const int t = t0 + j;
            const bool thit = (t >= ts0[0] && t < te[0]) ||
                              (t >= ts0[1] && t < te[1]);
            o.v[j] = fmaf(n.v[j], SA_NOISE_STD, thit ? 0.0f : s.v[j]);
        }
        stg256cs(op, o);
    }
}

extern "C" void kernel_launch(void* const* d_in, const int* in_sizes, int n_in,
                              void* d_out, int out_size) {
    const float* spec      = (const float*)d_in[0];
    const float* apply_u   = (const float*)d_in[1];
    const float* f_width_u = (const float*)d_in[2];
    const float* f_start_u = (const float*)d_in[3];
    const float* t_width_u = (const float*)d_in[4];
    const float* t_start_u = (const float*)d_in[5];
    const float* noise     = (const float*)d_in[6];
    float* out             = (float*)d_out;

    specaug_kernel<<<SA_GRID, 256>>>(spec, apply_u, f_width_u, f_start_u,
                                     t_width_u, t_start_u, noise, out);
}

// round 5
// speedup vs baseline: 1.0173x; 1.0173x over previous
#include <cuda_runtime.h>

// SpectrogramAugmentation: B=64, C=2, F=128, T=2048, fp32. HBM-bound at the
// traffic floor (~293 MB). R5: back to contiguous block->row mapping (R4's
// grid-stride broke DRAM locality), but 2 adjacent rows per block so each
// thread keeps up to 4 independent LDG.256 in flight and wave count halves.
// Traffic-minimal branches per row:
//   - non-apply batch: out = spec                (no noise read)
//   - apply + freq-masked row: out = 0.01*noise  (no spec read)
//   - apply + kept row: out = (timekeep? spec:0) + 0.01*noise

#define SA_B 64
#define SA_C 2
#define SA_F 128
#define SA_T 2048
#define SA_FREQ_PARAM 20.0f
#define SA_TIME_PARAM 40.0f
#define SA_NOISE_STD 0.01f
#define SA_P_APPLY 0.5f

struct f8 { float v[8]; };

__device__ __forceinline__ f8 ldg256cs(const float* p) {
    f8 r;
    asm volatile("ld.global.cs.v8.f32 {%0,%1,%2,%3,%4,%5,%6,%7}, [%8];"
                 : "=f"(r.v[0]), "=f"(r.v[1]), "=f"(r.v[2]), "=f"(r.v[3]),
                   "=f"(r.v[4]), "=f"(r.v[5]), "=f"(r.v[6]), "=f"(r.v[7])
                 : "l"(p));
    return r;
}

__device__ __forceinline__ void stg256cs(float* p, const f8& r) {
    asm volatile("st.global.cs.v8.f32 [%0], {%1,%2,%3,%4,%5,%6,%7,%8};"
                 :: "l"(p),
                    "f"(r.v[0]), "f"(r.v[1]), "f"(r.v[2]), "f"(r.v[3]),
                    "f"(r.v[4]), "f"(r.v[5]), "f"(r.v[6]), "f"(r.v[7])
                 : "memory");
}

__device__ __forceinline__ bool freq_hit(const float* __restrict__ f_width_u,
                                         const float* __restrict__ f_start_u,
                                         int b, int f) {
    bool fhit = false;
    #pragma unroll
    for (int k = 0; k < 2; k++) {
        const int   w   = (int)floorf(__ldg(&f_width_u[b * 2 + k]) * SA_FREQ_PARAM);
        const float rng = (float)(SA_F - w);
        const int   s0  = (int)floorf(__ldg(&f_start_u[b * 2 + k]) * rng);
        fhit = fhit || (f >= s0 && f < s0 + w);
    }
    return fhit;
}

__global__ __launch_bounds__(256)
void specaug_kernel(const float* __restrict__ spec,
                    const float* __restrict__ apply_u,
                    const float* __restrict__ f_width_u,
                    const float* __restrict__ f_start_u,
                    const float* __restrict__ t_width_u,
                    const float* __restrict__ t_start_u,
                    const float* __restrict__ noise,
                    float* __restrict__ out) {
    const int row0 = blockIdx.x * 2;            // two adjacent rows per block
    const int b    = row0 >> 8;                 // row / (C*F); same for both rows
    const int t0   = threadIdx.x * 8;           // this thread's 8 time samples
    const long long base0 = (long long)row0 * SA_T + t0;
    const long long base1 = base0 + SA_T;

    const float* sp0 = spec + base0;
    const float* sp1 = spec + base1;
    float*       op0 = out  + base0;
    float*       op1 = out  + base1;

    const bool apply = (__ldg(&apply_u[b]) <= SA_P_APPLY);
    if (!apply) {
        // exact passthrough: no noise read; both loads in flight together
        const f8 s0 = ldg256cs(sp0);
        const f8 s1 = ldg256cs(sp1);
        stg256cs(op0, s0);
        stg256cs(op1, s1);
        return;
    }

    const int f0 = row0 & (SA_F - 1);
    const int f1 = (row0 + 1) & (SA_F - 1);
    const bool fhit0 = freq_hit(f_width_u, f_start_u, b, f0);
    const bool fhit1 = freq_hit(f_width_u, f_start_u, b, f1);

    // --- time masks (2 masks, clamp_min_one on range); shared by both rows ---
    int ts0[2], te[2];
    #pragma unroll
    for (int k = 0; k < 2; k++) {
        const int w = (int)floorf(__ldg(&t_width_u[b * 2 + k]) * SA_TIME_PARAM);
        float rng = (float)(SA_T - w);
        if (rng < 1.0f) rng = 1.0f;
        const int s0 = (int)floorf(__ldg(&t_start_u[b * 2 + k]) * rng);
        ts0[k] = s0;
        te[k]  = s0 + w;
    }

    bool thit[8];
    #pragma unroll
    for (int j = 0; j < 8; j++) {
        const int t = t0 + j;
        thit[j] = (t >= ts0[0] && t < te[0]) || (t >= ts0[1] && t < te[1]);
    }

    // Issue all needed loads first (max MLP), then compute + store.
    const f8 n0 = ldg256cs(noise + base0);
    const f8 n1 = ldg256cs(noise + base1);
    f8 s0, s1;
    if (!fhit0) s0 = ldg256cs(sp0);
    if (!fhit1) s1 = ldg256cs(sp1);

    f8 o0, o1;
    if (fhit0) {
        #pragma unroll
        for (int j = 0; j < 8; j++) o0.v[j] = n0.v[j] * SA_NOISE_STD;
    } else {
        #pragma unroll
        for (int j = 0; j < 8; j++)
            o0.v[j] = fmaf(n0.v[j], SA_NOISE_STD, thit[j] ? 0.0f : s0.v[j]);
    }
    if (fhit1) {
        #pragma unroll
        for (int j = 0; j < 8; j++) o1.v[j] = n1.v[j] * SA_NOISE_STD;
    } else {
        #pragma unroll
        for (int j = 0; j < 8; j++)
            o1.v[j] = fmaf(n1.v[j], SA_NOISE_STD, thit[j] ? 0.0f : s1.v[j]);
    }
    stg256cs(op0, o0);
    stg256cs(op1, o1);
}

extern "C" void kernel_launch(void* const* d_in, const int* in_sizes, int n_in,
                              void* d_out, int out_size) {
    const float* spec      = (const float*)d_in[0];
    const float* apply_u   = (const float*)d_in[1];
    const float* f_width_u = (const float*)d_in[2];
    const float* f_start_u = (const float*)d_in[3];
    const float* t_width_u = (const float*)d_in[4];
    const float* t_start_u = (const float*)d_in[5];
    const float* noise     = (const float*)d_in[6];
    float* out             = (float*)d_out;

    const int blocks = (SA_B * SA_C * SA_F) / 2;   // 8192, 2 adjacent rows each
    specaug_kernel<<<blocks, 256>>>(spec, apply_u, f_width_u, f_start_u,
                                    t_width_u, t_start_u, noise, out);
}

// round 6
// speedup vs baseline: 1.0476x; 1.0298x over previous
#include <cuda_runtime.h>

// SpectrogramAugmentation: B=64, C=2, F=128, T=2048, fp32. HBM-bound at the
// traffic floor (~293 MB), rate ~79% of spec (2R:1W mixed-stream limited).
// R6: R3's proven per-thread code (1 row per 256-thread group, one v8 load per
// buffer, 32 regs) with 512-thread blocks covering 2 adjacent rows — halves
// block count / wave transitions without touching register pressure (R5's
// failure) or address locality (R4's failure).
// Traffic-minimal branches per row:
//   - non-apply batch: out = spec                (no noise read)
//   - apply + freq-masked row: out = 0.01*noise  (no spec read)
//   - apply + kept row: out = (timekeep? spec:0) + 0.01*noise

#define SA_B 64
#define SA_C 2
#define SA_F 128
#define SA_T 2048
#define SA_FREQ_PARAM 20.0f
#define SA_TIME_PARAM 40.0f
#define SA_NOISE_STD 0.01f
#define SA_P_APPLY 0.5f

struct f8 { float v[8]; };

__device__ __forceinline__ f8 ldg256cs(const float* p) {
    f8 r;
    asm volatile("ld.global.cs.v8.f32 {%0,%1,%2,%3,%4,%5,%6,%7}, [%8];"
                 : "=f"(r.v[0]), "=f"(r.v[1]), "=f"(r.v[2]), "=f"(r.v[3]),
                   "=f"(r.v[4]), "=f"(r.v[5]), "=f"(r.v[6]), "=f"(r.v[7])
                 : "l"(p));
    return r;
}

__device__ __forceinline__ void stg256cs(float* p, const f8& r) {
    asm volatile("st.global.cs.v8.f32 [%0], {%1,%2,%3,%4,%5,%6,%7,%8};"
                 :: "l"(p),
                    "f"(r.v[0]), "f"(r.v[1]), "f"(r.v[2]), "f"(r.v[3]),
                    "f"(r.v[4]), "f"(r.v[5]), "f"(r.v[6]), "f"(r.v[7])
                 : "memory");
}

__global__ __launch_bounds__(512)
void specaug_kernel(const float* __restrict__ spec,
                    const float* __restrict__ apply_u,
                    const float* __restrict__ f_width_u,
                    const float* __restrict__ f_start_u,
                    const float* __restrict__ t_width_u,
                    const float* __restrict__ t_start_u,
                    const float* __restrict__ noise,
                    float* __restrict__ out) {
    // threads 0-255 -> row0, threads 256-511 -> row1 (adjacent rows, same batch)
    const int row = blockIdx.x * 2 + (threadIdx.x >> 8);
    const int f   = row & (SA_F - 1);
    const int b   = row >> 8;                    // row / (C*F)
    const int t0  = (threadIdx.x & 255) * 8;     // this thread's 8 time samples
    const long long base = (long long)row * SA_T + t0;

    const float* sp = spec + base;
    float*       op = out  + base;

    const bool apply = (__ldg(&apply_u[b]) <= SA_P_APPLY);
    if (!apply) {
        // exact passthrough: no noise read
        stg256cs(op, ldg256cs(sp));
        return;
    }

    const float* np = noise + base;

    // --- frequency mask for this f (2 masks, no clamp_min_one) ---
    bool fhit = false;
    #pragma unroll
    for (int k = 0; k < 2; k++) {
        const int   w   = (int)floorf(__ldg(&f_width_u[b * 2 + k]) * SA_FREQ_PARAM);
        const float rng = (float)(SA_F - w);
        const int   s0  = (int)floorf(__ldg(&f_start_u[b * 2 + k]) * rng);
        fhit = fhit || (f >= s0 && f < s0 + w);
    }

    if (fhit) {
        // whole row frequency-masked: out = 0.01*noise, no spec read
        const f8 n = ldg256cs(np);
        f8 o;
        #pragma unroll
        for (int j = 0; j < 8; j++) o.v[j] = n.v[j] * SA_NOISE_STD;
        stg256cs(op, o);
        return;
    }

    // --- time masks (2 masks, clamp_min_one on range) ---
    int ts0[2], te[2];
    #pragma unroll
    for (int k = 0; k < 2; k++) {
        const int w = (int)floorf(__ldg(&t_width_u[b * 2 + k]) * SA_TIME_PARAM);
        float rng = (float)(SA_T - w);
        if (rng < 1.0f) rng = 1.0f;
        const int s0 = (int)floorf(__ldg(&t_start_u[b * 2 + k]) * rng);
        ts0[k] = s0;
        te[k]  = s0 + w;
    }

    const f8 s = ldg256cs(sp);
    const f8 n = ldg256cs(np);
    f8 o;
    #pragma unroll
    for (int j = 0; j < 8; j++) {
        const int t = t0 + j;
        const bool thit = (t >= ts0[0] && t < te[0]) ||
                          (t >= ts0[1] && t < te[1]);
        o.v[j] = fmaf(n.v[j], SA_NOISE_STD, thit ? 0.0f : s.v[j]);
    }
    stg256cs(op, o);
}

extern "C" void kernel_launch(void* const* d_in, const int* in_sizes, int n_in,
                              void* d_out, int out_size) {
    const float* spec      = (const float*)d_in[0];
    const float* apply_u   = (const float*)d_in[1];
    const float* f_width_u = (const float*)d_in[2];
    const float* f_start_u = (const float*)d_in[3];
    const float* t_width_u = (const float*)d_in[4];
    const float* t_start_u = (const float*)d_in[5];
    const float* noise     = (const float*)d_in[6];
    float* out             = (float*)d_out;

    const int blocks = (SA_B * SA_C * SA_F) / 2;   // 8192 blocks, 2 rows each
    specaug_kernel<<<blocks, 512>>>(spec, apply_u, f_width_u, f_start_u,
                                    t_width_u, t_start_u, noise, out);
}